// round 1
// baseline (speedup 1.0000x reference)
#include <cuda_runtime.h>
#include <math_constants.h>

// Problem constants
#define Bsz 8
#define Nn  1032
#define Cc  768
#define Hh  12
#define HD  64
#define PFX 8

// Scratch (static device allocations; cudaMalloc is forbidden)
__device__ float g_K[(size_t)Bsz * Hh * Nn * HD];   // K laid out [b,h,n,d]
__device__ float g_V[(size_t)Bsz * Hh * Nn * HD];   // V laid out [b,h,n,d]
__device__ float g_AO[(size_t)Bsz * Nn * Cc];       // attention output [b,n,c]
__device__ float g_lut[64];                          // gaussian 1-D window LUT

__global__ void init_lut_kernel() {
    int t = threadIdx.x;
    if (t < 63) {
        const float c = 0.14142135623730951f;   // 1/(5*sqrt(2))
        float x = (float)(t - 31) * c;
        g_lut[t] = expf(-x * x);
    }
}

// ---------------------------------------------------------------------------
// Generic NT GEMM: C[m,n] = sum_k A[m,k]*Bm[n,k] + bias[n]
// 64x64 tile, K-tile 16, 256 threads, 4x4 microtile, software-pipelined loads.
// MODE 1: A = x param, scatter output into g_K / g_V ([b,h,n,d] layout)
// MODE 2: A = g_AO, plain row-major write to Cout
// ---------------------------------------------------------------------------
template <int MODE>
__global__ void gemm_nt(const float* __restrict__ A,
                        const float* __restrict__ Bm,
                        const float* __restrict__ bias,
                        float* __restrict__ Cout,
                        int M, int Nout, int K) {
    __shared__ float As[16][64];
    __shared__ float Bs[16][64];

    const float* Ap = (MODE == 2) ? (const float*)g_AO : A;

    int tid = threadIdx.x;
    int tx = tid & 15;
    int ty = tid >> 4;
    int m0 = blockIdx.y * 64;
    int n0 = blockIdx.x * 64;

    int lr = tid >> 2;          // 0..63  row within tile
    int lc = (tid & 3) << 2;    // 0,4,8,12 col (float4)

    const float* Aptr = Ap + (size_t)(m0 + lr) * K + lc;
    const float* Bptr = Bm + (size_t)(n0 + lr) * K + lc;

    float acc[4][4] = {};

    float4 av = *(const float4*)(Aptr);
    float4 bv = *(const float4*)(Bptr);

    for (int k0 = 0; k0 < K; k0 += 16) {
        __syncthreads();
        As[lc + 0][lr] = av.x; As[lc + 1][lr] = av.y;
        As[lc + 2][lr] = av.z; As[lc + 3][lr] = av.w;
        Bs[lc + 0][lr] = bv.x; Bs[lc + 1][lr] = bv.y;
        Bs[lc + 2][lr] = bv.z; Bs[lc + 3][lr] = bv.w;
        __syncthreads();

        if (k0 + 16 < K) {
            av = *(const float4*)(Aptr + k0 + 16);
            bv = *(const float4*)(Bptr + k0 + 16);
        }

#pragma unroll
        for (int kk = 0; kk < 16; kk++) {
            float4 a4 = *(const float4*)&As[kk][ty * 4];
            float4 b4 = *(const float4*)&Bs[kk][tx * 4];
            float ar[4] = {a4.x, a4.y, a4.z, a4.w};
            float br[4] = {b4.x, b4.y, b4.z, b4.w};
#pragma unroll
            for (int i = 0; i < 4; i++)
#pragma unroll
                for (int j = 0; j < 4; j++)
                    acc[i][j] += ar[i] * br[j];
        }
    }

#pragma unroll
    for (int i = 0; i < 4; i++) {
        int m = m0 + ty * 4 + i;
#pragma unroll
        for (int j = 0; j < 4; j++) {
            int n = n0 + tx * 4 + j;
            float v = acc[i][j] + bias[n];
            if (MODE == 2) {
                Cout[(size_t)m * Nout + n] = v;
            } else {
                int bb = m / Nn;
                int nn = m - bb * Nn;
                if (n < Cc) {
                    int h = n >> 6, d = n & 63;
                    g_K[(((size_t)bb * Hh + h) * Nn + nn) * HD + d] = v;
                } else {
                    int o = n - Cc;
                    int h = o >> 6, d = o & 63;
                    g_V[(((size_t)bb * Hh + h) * Nn + nn) * HD + d] = v;
                }
            }
        }
    }
}

// ---------------------------------------------------------------------------
// Fused attention: for each (b,h, 64-row i-tile):
//   S = (K_i . K_j^T)*scale + add(i,j);  online softmax;  O += P @ V_j
// 256 threads (16x16), 4x4 microtiles. Smem: Ki + (Kj reused as P) + Vj = 48KB.
// ---------------------------------------------------------------------------
__global__ void attn_fused() {
    __shared__ float Ki[64 * 64];
    __shared__ float KjP[64 * 64];   // holds K_j tile, then reused for P tile
    __shared__ float Vj[64 * 64];

    int tid = threadIdx.x;
    int tx = tid & 15;
    int ty = tid >> 4;
    int it = blockIdx.x;
    int h  = blockIdx.y;
    int b  = blockIdx.z;

    const float* Kbh = g_K + ((size_t)(b * Hh + h)) * Nn * HD;
    const float* Vbh = g_V + ((size_t)(b * Hh + h)) * Nn * HD;
    int i0 = it * 64;

    // Load Ki tile (zero-fill rows beyond N)
    for (int idx = tid; idx < 64 * 16; idx += 256) {
        int r = idx >> 4;
        int c4 = (idx & 15) << 2;
        int gi = i0 + r;
        float4 v = (gi < Nn) ? *(const float4*)(Kbh + (size_t)gi * HD + c4)
                             : make_float4(0.f, 0.f, 0.f, 0.f);
        *(float4*)&Ki[r * 64 + c4] = v;
    }

    float o[4][4] = {};
    float mrun[4], lrun[4];
#pragma unroll
    for (int i = 0; i < 4; i++) { mrun[i] = -CUDART_INF_F; lrun[i] = 0.f; }

    for (int jt = 0; jt < 17; jt++) {
        int j0 = jt * 64;
        __syncthreads();   // prior O-update reads of KjP/Vj complete
        for (int idx = tid; idx < 64 * 16; idx += 256) {
            int r = idx >> 4;
            int c4 = (idx & 15) << 2;
            int gj = j0 + r;
            float4 kv4, vv4;
            if (gj < Nn) {
                kv4 = *(const float4*)(Kbh + (size_t)gj * HD + c4);
                vv4 = *(const float4*)(Vbh + (size_t)gj * HD + c4);
            } else {
                kv4 = make_float4(0.f, 0.f, 0.f, 0.f);
                vv4 = kv4;
            }
            *(float4*)&KjP[r * 64 + c4] = kv4;
            *(float4*)&Vj[r * 64 + c4]  = vv4;
        }
        __syncthreads();

        // S = Ki . Kj^T
        float s[4][4] = {};
        for (int d = 0; d < 64; d += 4) {
            float4 a4[4], b4[4];
#pragma unroll
            for (int i = 0; i < 4; i++)
                a4[i] = *(const float4*)&Ki[(ty * 4 + i) * 64 + d];
#pragma unroll
            for (int j = 0; j < 4; j++)
                b4[j] = *(const float4*)&KjP[(tx * 4 + j) * 64 + d];
#pragma unroll
            for (int i = 0; i < 4; i++)
#pragma unroll
                for (int j = 0; j < 4; j++)
                    s[i][j] += a4[i].x * b4[j].x + a4[i].y * b4[j].y +
                               a4[i].z * b4[j].z + a4[i].w * b4[j].w;
        }

        // scale + gaussian additive bias + mask
#pragma unroll
        for (int i = 0; i < 4; i++) {
            int gi = i0 + ty * 4 + i;
#pragma unroll
            for (int j = 0; j < 4; j++) {
                int gj = j0 + tx * 4 + j;
                float val = s[i][j] * 0.125f;
                if (gi >= PFX && gj >= PFX && gi < Nn && gj < Nn) {
                    int ia = gi - PFX, ja = gj - PFX;
                    val += __ldg(&g_lut[(ia >> 5) - (ja >> 5) + 31]) *
                           __ldg(&g_lut[(ia & 31) - (ja & 31) + 31]);
                }
                if (gj >= Nn) val = -CUDART_INF_F;
                s[i][j] = val;
            }
        }

        // online softmax (row groups of 16 lanes share a half-warp)
        float fac[4];
#pragma unroll
        for (int i = 0; i < 4; i++) {
            float mt = s[i][0];
#pragma unroll
            for (int j = 1; j < 4; j++) mt = fmaxf(mt, s[i][j]);
#pragma unroll
            for (int off = 8; off >= 1; off >>= 1)
                mt = fmaxf(mt, __shfl_xor_sync(0xffffffffu, mt, off));
            float mnew = fmaxf(mrun[i], mt);
            fac[i] = __expf(mrun[i] - mnew);
            mrun[i] = mnew;
            float lt = 0.f;
#pragma unroll
            for (int j = 0; j < 4; j++) {
                s[i][j] = __expf(s[i][j] - mnew);
                lt += s[i][j];
            }
#pragma unroll
            for (int off = 8; off >= 1; off >>= 1)
                lt += __shfl_xor_sync(0xffffffffu, lt, off);
            lrun[i] = lrun[i] * fac[i] + lt;
        }

        __syncthreads();   // everyone done reading KjP as K
#pragma unroll
        for (int i = 0; i < 4; i++)
            *(float4*)&KjP[(ty * 4 + i) * 64 + tx * 4] =
                make_float4(s[i][0], s[i][1], s[i][2], s[i][3]);
        __syncthreads();

#pragma unroll
        for (int i = 0; i < 4; i++)
#pragma unroll
            for (int j = 0; j < 4; j++) o[i][j] *= fac[i];

        // O += P @ V
        for (int jd = 0; jd < 64; jd += 4) {
            float pr[4][4];
#pragma unroll
            for (int i = 0; i < 4; i++) {
                float4 t = *(const float4*)&KjP[(ty * 4 + i) * 64 + jd];
                pr[i][0] = t.x; pr[i][1] = t.y; pr[i][2] = t.z; pr[i][3] = t.w;
            }
#pragma unroll
            for (int r = 0; r < 4; r++) {
                float4 v4 = *(const float4*)&Vj[(jd + r) * 64 + tx * 4];
                float vr[4] = {v4.x, v4.y, v4.z, v4.w};
#pragma unroll
                for (int i = 0; i < 4; i++)
#pragma unroll
                    for (int j = 0; j < 4; j++)
                        o[i][j] += pr[i][r] * vr[j];
            }
        }
    }

    // normalize + write [b,n,c]
#pragma unroll
    for (int i = 0; i < 4; i++) {
        int gi = i0 + ty * 4 + i;
        if (gi < Nn) {
            float inv = 1.f / lrun[i];
            float4 w = make_float4(o[i][0] * inv, o[i][1] * inv,
                                   o[i][2] * inv, o[i][3] * inv);
            *(float4*)&g_AO[((size_t)b * Nn + gi) * Cc + h * HD + tx * 4] = w;
        }
    }
}

extern "C" void kernel_launch(void* const* d_in, const int* in_sizes, int n_in,
                              void* d_out, int out_size) {
    (void)in_sizes; (void)n_in; (void)out_size;
    const float* x      = (const float*)d_in[0];
    const float* qkv_w  = (const float*)d_in[1];
    const float* qkv_b  = (const float*)d_in[2];
    const float* proj_w = (const float*)d_in[3];
    const float* proj_b = (const float*)d_in[4];
    float* out = (float*)d_out;

    init_lut_kernel<<<1, 64>>>();

    // KV GEMM: skip the dead Q slab (rows [0,768) of qkv_w are never used)
    gemm_nt<1><<<dim3(2 * Cc / 64, (Bsz * Nn) / 64), 256>>>(
        x, qkv_w + (size_t)Cc * Cc, qkv_b + Cc, nullptr,
        Bsz * Nn, 2 * Cc, Cc);

    attn_fused<<<dim3(17, Hh, Bsz), 256>>>();

    // Projection GEMM
    gemm_nt<2><<<dim3(Cc / 64, (Bsz * Nn) / 64), 256>>>(
        nullptr, proj_w, proj_b, out,
        Bsz * Nn, Cc, Cc);
}

// round 2
// speedup vs baseline: 4.0906x; 4.0906x over previous
#include <cuda_runtime.h>
#include <math_constants.h>

// Problem constants
#define Bsz 8
#define Nn  1032
#define Cc  768
#define Hh  12
#define HD  64
#define PFX 8

// Scratch (static device allocations; cudaMalloc is forbidden)
__device__ float g_K[(size_t)Bsz * Hh * Nn * HD];   // K laid out [b,h,n,d]
__device__ float g_V[(size_t)Bsz * Hh * Nn * HD];   // V laid out [b,h,n,d]
__device__ float g_AO[(size_t)Bsz * Nn * Cc];       // attention output [b,n,c]
__device__ float g_lut[64];                          // gaussian 1-D window LUT

__global__ void init_lut_kernel() {
    int t = threadIdx.x;
    if (t < 63) {
        const float c = 0.14142135623730951f;   // 1/(5*sqrt(2))
        float x = (float)(t - 31) * c;
        g_lut[t] = expf(-x * x);
    }
}

// ---------------------------------------------------------------------------
// tf32 mma.sync helpers
// ---------------------------------------------------------------------------
__device__ __forceinline__ float cvt_tf32(float x) {
    unsigned r;
    asm("cvt.rna.tf32.f32 %0, %1;" : "=r"(r) : "f"(x));
    return __uint_as_float(r);
}
__device__ __forceinline__ float4 cvt_tf32_4(float4 v) {
    return make_float4(cvt_tf32(v.x), cvt_tf32(v.y), cvt_tf32(v.z), cvt_tf32(v.w));
}
__device__ __forceinline__ void ldm4(unsigned r[4], unsigned addr) {
    asm volatile("ldmatrix.sync.aligned.m8n8.x4.shared.b16 {%0,%1,%2,%3}, [%4];"
                 : "=r"(r[0]), "=r"(r[1]), "=r"(r[2]), "=r"(r[3]) : "r"(addr));
}
__device__ __forceinline__ void mma8(float c[4], const unsigned a[4],
                                     unsigned b0, unsigned b1) {
    asm volatile(
        "mma.sync.aligned.m16n8k8.row.col.f32.tf32.tf32.f32 "
        "{%0,%1,%2,%3},{%4,%5,%6,%7},{%8,%9},{%0,%1,%2,%3};"
        : "+f"(c[0]), "+f"(c[1]), "+f"(c[2]), "+f"(c[3])
        : "r"(a[0]), "r"(a[1]), "r"(a[2]), "r"(a[3]), "r"(b0), "r"(b1));
}
__device__ __forceinline__ unsigned smem_u32(const void* p) {
    return (unsigned)__cvta_generic_to_shared(p);
}

// ---------------------------------------------------------------------------
// tf32 NT GEMM: C[m,n] = sum_k A[m,k]*Bm[n,k] + bias[n]
// 128x128 tile, k-tile 32, 256 threads (8 warps), warp tile 64x32.
// MODE 1: scatter output into g_K / g_V ([b,h,n,d]).  MODE 2: row-major Cout.
// ---------------------------------------------------------------------------
#define SAS 36   // smem row stride in floats (144B = 9 * 16B -> conflict-free ldmatrix)

template <int MODE>
__global__ void __launch_bounds__(256) gemm_tf32(
        const float* __restrict__ A, const float* __restrict__ Bm,
        const float* __restrict__ bias, float* __restrict__ Cout,
        int M, int Nout, int K) {
    __shared__ float sA[128 * SAS];
    __shared__ float sB[128 * SAS];

    const float* Ap = (MODE == 2) ? (const float*)g_AO : A;

    int tid = threadIdx.x;
    int lane = tid & 31;
    int w = tid >> 5;
    int wm = w >> 2, wn = w & 3;          // warp grid 2 x 4
    int m0 = blockIdx.y * 128, n0 = blockIdx.x * 128;

    // gmem fill mapping: 128 rows x 32 floats, 2 threads/row x 16 floats
    int frow = tid >> 1;
    int fcol = (tid & 1) * 16;
    const float* Aptr = Ap + (size_t)(m0 + frow) * K + fcol;
    const float* Bptr = Bm + (size_t)(n0 + frow) * K + fcol;
    bool aval = (m0 + frow) < M;

    float4 ra[4], rb[4];
#pragma unroll
    for (int i = 0; i < 4; i++) {
        ra[i] = aval ? *(const float4*)(Aptr + i * 4) : make_float4(0.f, 0.f, 0.f, 0.f);
        rb[i] = *(const float4*)(Bptr + i * 4);
    }

    float acc[4][4][4] = {};

    unsigned sAu = smem_u32(sA), sBu = smem_u32(sB);
    int l7 = lane & 7, q = lane >> 3;
    unsigned aBase = sAu + (((wm * 64 + l7 + (q & 1) * 8) * SAS + (q >> 1) * 4) << 2);
    unsigned bBase = sBu + (((wn * 32 + l7 + (q >> 1) * 8) * SAS + (q & 1) * 4) << 2);

    int nkt = K / 32;
    for (int kt = 0; kt < nkt; kt++) {
        __syncthreads();
#pragma unroll
        for (int i = 0; i < 4; i++) {
            *(float4*)&sA[frow * SAS + fcol + i * 4] = cvt_tf32_4(ra[i]);
            *(float4*)&sB[frow * SAS + fcol + i * 4] = cvt_tf32_4(rb[i]);
        }
        __syncthreads();
        if (kt + 1 < nkt) {
#pragma unroll
            for (int i = 0; i < 4; i++) {
                ra[i] = aval ? *(const float4*)(Aptr + (kt + 1) * 32 + i * 4)
                             : make_float4(0.f, 0.f, 0.f, 0.f);
                rb[i] = *(const float4*)(Bptr + (kt + 1) * 32 + i * 4);
            }
        }
#pragma unroll
        for (int k8 = 0; k8 < 4; k8++) {
            unsigned af[4][4], bf[2][4];
#pragma unroll
            for (int mi = 0; mi < 4; mi++)
                ldm4(af[mi], aBase + mi * (16 * SAS * 4) + k8 * 32);
#pragma unroll
            for (int nj = 0; nj < 2; nj++)
                ldm4(bf[nj], bBase + nj * (16 * SAS * 4) + k8 * 32);
#pragma unroll
            for (int mi = 0; mi < 4; mi++)
#pragma unroll
                for (int ni = 0; ni < 4; ni++)
                    mma8(acc[mi][ni], af[mi],
                         bf[ni >> 1][(ni & 1) * 2], bf[ni >> 1][(ni & 1) * 2 + 1]);
        }
    }

    // epilogue
    int r0base = m0 + wm * 64 + (lane >> 2);
    int cbase = n0 + wn * 32 + 2 * (lane & 3);
#pragma unroll
    for (int mi = 0; mi < 4; mi++) {
#pragma unroll
        for (int ni = 0; ni < 4; ni++) {
            int c = cbase + ni * 8;
            float bv0 = bias[c], bv1 = bias[c + 1];
#pragma unroll
            for (int half = 0; half < 2; half++) {
                int m = r0base + mi * 16 + half * 8;
                if (m >= M) continue;
                float v0 = acc[mi][ni][half * 2 + 0] + bv0;
                float v1 = acc[mi][ni][half * 2 + 1] + bv1;
                if (MODE == 2) {
                    Cout[(size_t)m * Nout + c]     = v0;
                    Cout[(size_t)m * Nout + c + 1] = v1;
                } else {
                    int bb = m / Nn;
                    int nn = m - bb * Nn;
#pragma unroll
                    for (int e = 0; e < 2; e++) {
                        int n = c + e;
                        float v = e ? v1 : v0;
                        if (n < Cc) {
                            int h = n >> 6, d = n & 63;
                            g_K[(((size_t)bb * Hh + h) * Nn + nn) * HD + d] = v;
                        } else {
                            int o = n - Cc;
                            int h = o >> 6, d = o & 63;
                            g_V[(((size_t)bb * Hh + h) * Nn + nn) * HD + d] = v;
                        }
                    }
                }
            }
        }
    }
}

// ---------------------------------------------------------------------------
// Fused flash attention on tf32 mma. 128 threads (4 warps), i-tile 64 rows.
// Warp w owns rows [w*16, w*16+16). Dynamic smem: Ki, Kj, Vt, Ps (64x68 each).
// ---------------------------------------------------------------------------
#define SKS 68   // 272B = 17 * 16B -> conflict-free ldmatrix

__global__ void __launch_bounds__(128) attn_tf32() {
    extern __shared__ float smem[];
    float* sKi = smem;
    float* sKj = sKi + 64 * SKS;
    float* sVt = sKj + 64 * SKS;
    float* sPs = sVt + 64 * SKS;

    int tid = threadIdx.x;
    int lane = tid & 31;
    int w = tid >> 5;
    int it = blockIdx.x, h = blockIdx.y, b = blockIdx.z;
    int i0 = it * 64;

    const float* Kbh = g_K + ((size_t)(b * Hh + h)) * Nn * HD;
    const float* Vbh = g_V + ((size_t)(b * Hh + h)) * Nn * HD;

    // fill Ki (tf32-converted, zero beyond N)
    for (int idx = tid; idx < 64 * 16; idx += 128) {
        int r = idx >> 4, c4 = (idx & 15) << 2;
        int gi = i0 + r;
        float4 v = (gi < Nn) ? *(const float4*)(Kbh + (size_t)gi * HD + c4)
                             : make_float4(0.f, 0.f, 0.f, 0.f);
        *(float4*)&sKi[r * SKS + c4] = cvt_tf32_4(v);
    }

    float o[8][4] = {};
    float mrun0 = -CUDART_INF_F, mrun1 = -CUDART_INF_F;
    float lrun0 = 0.f, lrun1 = 0.f;

    unsigned sKiu = smem_u32(sKi), sKju = smem_u32(sKj);
    unsigned sVtu = smem_u32(sVt), sPsu = smem_u32(sPs);
    int l7 = lane & 7, q = lane >> 3;
    unsigned aOff = (((w * 16 + l7 + (q & 1) * 8) * SKS + (q >> 1) * 4) << 2);
    unsigned bOff = (((l7 + (q >> 1) * 8) * SKS + (q & 1) * 4) << 2);
    unsigned aKi = sKiu + aOff;
    unsigned aPs = sPsu + aOff;
    unsigned bKj = sKju + bOff;
    unsigned bVt = sVtu + bOff;

    int rloc0 = w * 16 + (lane >> 2);
    int rloc1 = rloc0 + 8;

    for (int jt = 0; jt < 17; jt++) {
        int j0 = jt * 64;
        __syncthreads();
        // fill Kj + transposed V
        for (int idx = tid; idx < 64 * 16; idx += 128) {
            int r = idx >> 4, c4 = (idx & 15) << 2;
            int gj = j0 + r;
            float4 kv, vv;
            if (gj < Nn) {
                kv = *(const float4*)(Kbh + (size_t)gj * HD + c4);
                vv = *(const float4*)(Vbh + (size_t)gj * HD + c4);
            } else {
                kv = make_float4(0.f, 0.f, 0.f, 0.f);
                vv = kv;
            }
            *(float4*)&sKj[r * SKS + c4] = cvt_tf32_4(kv);
            sVt[(c4 + 0) * SKS + r] = cvt_tf32(vv.x);
            sVt[(c4 + 1) * SKS + r] = cvt_tf32(vv.y);
            sVt[(c4 + 2) * SKS + r] = cvt_tf32(vv.z);
            sVt[(c4 + 3) * SKS + r] = cvt_tf32(vv.w);
        }
        __syncthreads();

        // S = Ki . Kj^T
        float s[8][4] = {};
#pragma unroll
        for (int k8 = 0; k8 < 8; k8++) {
            unsigned af[4];
            ldm4(af, aKi + k8 * 32);
#pragma unroll
            for (int n16 = 0; n16 < 4; n16++) {
                unsigned bf[4];
                ldm4(bf, bKj + n16 * (16 * SKS * 4) + k8 * 32);
                mma8(s[2 * n16 + 0], af, bf[0], bf[1]);
                mma8(s[2 * n16 + 1], af, bf[2], bf[3]);
            }
        }

        // scale + gaussian bias + mask
        int gi0 = i0 + rloc0, gi1 = i0 + rloc1;
#pragma unroll
        for (int f = 0; f < 8; f++) {
#pragma unroll
            for (int e = 0; e < 4; e++) {
                int gi = (e < 2) ? gi0 : gi1;
                int gj = j0 + f * 8 + 2 * (lane & 3) + (e & 1);
                float val = s[f][e] * 0.125f;
                if (gi >= PFX && gj >= PFX && gi < Nn && gj < Nn) {
                    int ia = gi - PFX, ja = gj - PFX;
                    val += __ldg(&g_lut[(ia >> 5) - (ja >> 5) + 31]) *
                           __ldg(&g_lut[(ia & 31) - (ja & 31) + 31]);
                }
                if (gj >= Nn) val = -CUDART_INF_F;
                s[f][e] = val;
            }
        }

        // online softmax: row gi0 owns s[f][0..1], row gi1 owns s[f][2..3]
        float mt0 = -CUDART_INF_F, mt1 = -CUDART_INF_F;
#pragma unroll
        for (int f = 0; f < 8; f++) {
            mt0 = fmaxf(mt0, fmaxf(s[f][0], s[f][1]));
            mt1 = fmaxf(mt1, fmaxf(s[f][2], s[f][3]));
        }
#pragma unroll
        for (int off = 1; off <= 2; off <<= 1) {
            mt0 = fmaxf(mt0, __shfl_xor_sync(0xffffffffu, mt0, off));
            mt1 = fmaxf(mt1, __shfl_xor_sync(0xffffffffu, mt1, off));
        }
        float mn0 = fmaxf(mrun0, mt0), mn1 = fmaxf(mrun1, mt1);
        float fac0 = __expf(mrun0 - mn0), fac1 = __expf(mrun1 - mn1);
        mrun0 = mn0; mrun1 = mn1;
        float st0 = 0.f, st1 = 0.f;
#pragma unroll
        for (int f = 0; f < 8; f++) {
            s[f][0] = __expf(s[f][0] - mn0);
            s[f][1] = __expf(s[f][1] - mn0);
            s[f][2] = __expf(s[f][2] - mn1);
            s[f][3] = __expf(s[f][3] - mn1);
            st0 += s[f][0] + s[f][1];
            st1 += s[f][2] + s[f][3];
        }
#pragma unroll
        for (int off = 1; off <= 2; off <<= 1) {
            st0 += __shfl_xor_sync(0xffffffffu, st0, off);
            st1 += __shfl_xor_sync(0xffffffffu, st1, off);
        }
        lrun0 = lrun0 * fac0 + st0;
        lrun1 = lrun1 * fac1 + st1;
#pragma unroll
        for (int f = 0; f < 8; f++) {
            o[f][0] *= fac0; o[f][1] *= fac0;
            o[f][2] *= fac1; o[f][3] *= fac1;
        }

        // stage P into smem (tf32) for re-load as A fragments
        int pc = 2 * (lane & 3);
#pragma unroll
        for (int f = 0; f < 8; f++) {
            sPs[rloc0 * SKS + f * 8 + pc]     = cvt_tf32(s[f][0]);
            sPs[rloc0 * SKS + f * 8 + pc + 1] = cvt_tf32(s[f][1]);
            sPs[rloc1 * SKS + f * 8 + pc]     = cvt_tf32(s[f][2]);
            sPs[rloc1 * SKS + f * 8 + pc + 1] = cvt_tf32(s[f][3]);
        }
        __syncthreads();

        // O += P @ V
#pragma unroll
        for (int k8 = 0; k8 < 8; k8++) {
            unsigned af[4];
            ldm4(af, aPs + k8 * 32);
#pragma unroll
            for (int n16 = 0; n16 < 4; n16++) {
                unsigned bf[4];
                ldm4(bf, bVt + n16 * (16 * SKS * 4) + k8 * 32);
                mma8(o[2 * n16 + 0], af, bf[0], bf[1]);
                mma8(o[2 * n16 + 1], af, bf[2], bf[3]);
            }
        }
    }

    // normalize + write [b,n,c]
    int gi0 = i0 + rloc0, gi1 = i0 + rloc1;
    float inv0 = 1.f / lrun0, inv1 = 1.f / lrun1;
    int cb = h * HD + 2 * (lane & 3);
#pragma unroll
    for (int f = 0; f < 8; f++) {
        int col = cb + f * 8;
        if (gi0 < Nn) {
            g_AO[((size_t)b * Nn + gi0) * Cc + col]     = o[f][0] * inv0;
            g_AO[((size_t)b * Nn + gi0) * Cc + col + 1] = o[f][1] * inv0;
        }
        if (gi1 < Nn) {
            g_AO[((size_t)b * Nn + gi1) * Cc + col]     = o[f][2] * inv1;
            g_AO[((size_t)b * Nn + gi1) * Cc + col + 1] = o[f][3] * inv1;
        }
    }
}

extern "C" void kernel_launch(void* const* d_in, const int* in_sizes, int n_in,
                              void* d_out, int out_size) {
    (void)in_sizes; (void)n_in; (void)out_size;
    const float* x      = (const float*)d_in[0];
    const float* qkv_w  = (const float*)d_in[1];
    const float* qkv_b  = (const float*)d_in[2];
    const float* proj_w = (const float*)d_in[3];
    const float* proj_b = (const float*)d_in[4];
    float* out = (float*)d_out;

    static bool attr_done = false;
    if (!attr_done) {
        cudaFuncSetAttribute(attn_tf32,
                             cudaFuncAttributeMaxDynamicSharedMemorySize,
                             4 * 64 * SKS * sizeof(float));
        attr_done = true;
    }

    init_lut_kernel<<<1, 64>>>();

    // KV GEMM (Q slab of qkv_w is dead code in the reference)
    gemm_tf32<1><<<dim3((2 * Cc) / 128, (Bsz * Nn + 127) / 128), 256>>>(
        x, qkv_w + (size_t)Cc * Cc, qkv_b + Cc, nullptr,
        Bsz * Nn, 2 * Cc, Cc);

    attn_tf32<<<dim3(17, Hh, Bsz), 128, 4 * 64 * SKS * sizeof(float)>>>();

    // Projection GEMM
    gemm_tf32<2><<<dim3(Cc / 128, (Bsz * Nn + 127) / 128), 256>>>(
        nullptr, proj_w, proj_b, out,
        Bsz * Nn, Cc, Cc);
}